// round 7
// baseline (speedup 1.0000x reference)
#include <cuda_runtime.h>
#include <cuda_fp16.h>
#include <cstdint>

#define DIM     256
#define NEMBED  512
#define NROWS   131072
#define OUT_ELEMS 33554432
#define LOSS_OFF  33554432
#define IND_OFF   33554433

#define BM 128
#define PANEL 32
#define NPANEL (NEMBED / PANEL)   // 16
#define KLD 264                   // halves per row; 528B stride = 4 banks mod 32
#define SCALE 2048.0f             // 2^11
#define INV_SCALE2 2.38418579e-07f // 2^-22 exact
#define MAXCAND 16

#define ROWB (KLD * 2)            // 528 B
#define OFF_AHI  0                                  // 128*528 = 67584
#define OFF_B    (OFF_AHI + BM * ROWB)              // 67584
#define BSTAGE   (PANEL * ROWB)                     // 16896 per stage (hi only)
#define OFF_SSQ  (OFF_B + 2 * BSTAGE)               // 101376 (512 f)
#define OFF_RSSQ (OFF_SSQ + NEMBED * 4)             // 103424 (128 f)
#define OFF_WROW (OFF_RSSQ + BM * 4)                // 103936 (128 f)
#define OFF_BEST (OFF_WROW + BM * 4)                // 104448 (128 i)
#define OFF_CIDX (OFF_BEST + BM * 4)                // 104960 (128*16 i)
#define OFF_CCNT (OFF_CIDX + BM * MAXCAND * 4)      // 113152 (128 i)
#define OFF_RED  (OFF_CCNT + BM * 4)                // 113664
#define SMEM_BYTES (OFF_RED + 32)                   // 113696

__device__ float  g_embed_n[NEMBED * DIM];
__device__ __half g_bh16[NEMBED * DIM];
__device__ float  g_ssq[NEMBED];
__device__ float  g_sum[DIM];
__device__ float  g_ssqsum;
__device__ float  g_diff;

__device__ __forceinline__ uint32_t smem_u32(const void* p) {
    uint32_t a;
    asm("{ .reg .u64 t; cvta.to.shared.u64 t, %1; cvt.u32.u64 %0, t; }" : "=r"(a) : "l"(p));
    return a;
}
__device__ __forceinline__ void mma_f16(float* d, uint32_t a0, uint32_t a1,
                                        uint32_t a2, uint32_t a3,
                                        uint32_t b0, uint32_t b1) {
    asm volatile(
        "mma.sync.aligned.m16n8k16.row.col.f32.f16.f16.f32 "
        "{%0,%1,%2,%3}, {%4,%5,%6,%7}, {%8,%9}, {%0,%1,%2,%3};"
        : "+f"(d[0]), "+f"(d[1]), "+f"(d[2]), "+f"(d[3])
        : "r"(a0), "r"(a1), "r"(a2), "r"(a3), "r"(b0), "r"(b1));
}
__device__ __forceinline__ void ldsm4(uint32_t& r0, uint32_t& r1,
                                      uint32_t& r2, uint32_t& r3, uint32_t addr) {
    asm volatile("ldmatrix.sync.aligned.m8n8.x4.shared.b16 {%0,%1,%2,%3}, [%4];"
                 : "=r"(r0), "=r"(r1), "=r"(r2), "=r"(r3) : "r"(addr));
}
__device__ __forceinline__ void cp16(uint32_t dst, const void* src) {
    asm volatile("cp.async.cg.shared.global [%0], [%1], 16;" :: "r"(dst), "l"(src) : "memory");
}
#define CP_COMMIT() asm volatile("cp.async.commit_group;" ::: "memory")
#define CP_WAIT0()  asm volatile("cp.async.wait_group 0;" ::: "memory")

// ---------------------------------------------------------------- init ----
__global__ void init_kernel() {
    int t = threadIdx.x;
    g_sum[t] = 0.0f;
    if (t == 0) { g_ssqsum = 0.0f; g_diff = 0.0f; }
}

// ------------------------------------- normalize + fp16 hi (scaled) ----
__global__ void normalize_kernel(const float* __restrict__ emb) {
    __shared__ float w[8];
    int r = blockIdx.x, t = threadIdx.x;
    float v = emb[r * DIM + t];
    float s = v * v;
    #pragma unroll
    for (int o = 16; o > 0; o >>= 1) s += __shfl_xor_sync(0xffffffffu, s, o);
    if ((t & 31) == 0) w[t >> 5] = s;
    __syncthreads();
    float sum = 0.0f;
    #pragma unroll
    for (int k = 0; k < 8; ++k) sum += w[k];
    float en = __fdiv_rn(v, __fsqrt_rn(sum));
    g_embed_n[r * DIM + t] = en;
    g_bh16[r * DIM + t] = __float2half_rn(en * SCALE);
    atomicAdd(&g_sum[t], en);

    float s2 = en * en;
    #pragma unroll
    for (int o = 16; o > 0; o >>= 1) s2 += __shfl_xor_sync(0xffffffffu, s2, o);
    __syncthreads();
    if ((t & 31) == 0) w[t >> 5] = s2;
    __syncthreads();
    if (t == 0) {
        float tot = 0.0f;
        #pragma unroll
        for (int k = 0; k < 8; ++k) tot += w[k];
        g_ssq[r] = tot;
        atomicAdd(&g_ssqsum, tot);
    }
}

// ------------------------------------------------------------- main ----
__global__ void __launch_bounds__(256, 2)
main_kernel(const float* __restrict__ input,
            float* __restrict__ out,
            float* __restrict__ ind_out) {
    extern __shared__ char sm[];
    const uint32_t smb = smem_u32(sm);
    __half* ahi   = (__half*)(sm + OFF_AHI);
    float*  ssq_s = (float*)(sm + OFF_SSQ);
    float*  rssq_s= (float*)(sm + OFF_RSSQ);
    float*  wrow_s= (float*)(sm + OFF_WROW);
    int*    best_s= (int*)(sm + OFF_BEST);
    int*    cidx  = (int*)(sm + OFF_CIDX);
    int*    ccnt  = (int*)(sm + OFF_CCNT);
    float*  red   = (float*)(sm + OFF_RED);

    const int tid = threadIdx.x;
    const int wid = tid >> 5;
    const int lid = tid & 31;
    const int lq  = lid >> 2;
    const int lr  = lid & 3;
    const size_t n0 = (size_t)blockIdx.x * BM;

    // ---- prefetch B panel 0 (hi) into stage 0 ----
    #pragma unroll
    for (int i = 0; i < 4; ++i) {
        int c = tid + i * 256;                   // 0..1023
        int r = c >> 5, ch = c & 31;
        cp16(smb + OFF_B + r * ROWB + ch * 16, g_bh16 + r * DIM + ch * 8);
    }
    CP_COMMIT();

    // ---- load input tile, scale by 2^11, hi split to fp16 ----
    #pragma unroll
    for (int i = 0; i < 32; ++i) {
        int slot = tid + i * 256;
        int m = slot >> 6, c4 = slot & 63;
        float4 v = *(const float4*)(input + (n0 + m) * DIM + c4 * 4);
        __half hx = __float2half_rn(v.x * SCALE);
        __half hy = __float2half_rn(v.y * SCALE);
        __half hz = __float2half_rn(v.z * SCALE);
        __half hw = __float2half_rn(v.w * SCALE);
        int ho = m * KLD + c4 * 4;
        *(__half2*)(ahi + ho)     = __halves2half2(hx, hy);
        *(__half2*)(ahi + ho + 2) = __halves2half2(hz, hw);
    }
    ssq_s[tid]       = g_ssq[tid];
    ssq_s[tid + 256] = g_ssq[tid + 256];
    if (tid < BM) ccnt[tid] = 0;

    // ---- per-row ||x||^2 (same arithmetic order as passing kernels) + W ----
    {
        int m = tid >> 1, half = tid & 1;
        const float* xr = input + (n0 + m) * DIM + half * 128;
        float s = 0.0f;
        #pragma unroll 8
        for (int k = 0; k < 128; ++k) s += xr[k] * xr[k];
        s += __shfl_xor_sync(0xffffffffu, s, 1);
        if (half == 0) {
            rssq_s[m] = s;
            wrow_s[m] = 0.02f * __fsqrt_rn(s) + 0.01f;   // >> rigorous 2*eps_v bound
        }
    }

    // ---- ldmatrix addresses ----
    const int rowin = lid & 7;
    const int mi    = lid >> 3;
    const int aRow  = wid * 16 + rowin + 8 * (mi & 1);
    const uint32_t aHiA = smb + OFF_AHI + (uint32_t)(aRow * ROWB + (mi >> 1) * 16);
    const uint32_t bOff0 = (uint32_t)((8 * (0 + (mi >> 1)) + rowin) * ROWB + (mi & 1) * 16);
    const uint32_t bOff1 = (uint32_t)((8 * (2 + (mi >> 1)) + rowin) * ROWB + (mi & 1) * 16);

    const int r0 = wid * 16 + lq;
    float bv0 = -3.4e38f, bv1 = -3.4e38f;
    const float wr0 = wrow_s[r0];        // written by this thread's pair before; safe? (no: other thread) 
    // NOTE: wrow_s written by threads m*2; need sync before reading -> read after first __syncthreads below.

    float w0 = 0.0f, w1 = 0.0f;
    bool wload = false;

    for (int p = 0; p < NPANEL; ++p) {
        CP_WAIT0();
        __syncthreads();
        if (!wload) { w0 = wrow_s[r0]; w1 = wrow_s[r0 + 8]; wload = true; }
        if (p + 1 < NPANEL) {
            const int np = p + 1, st = np & 1;
            #pragma unroll
            for (int i = 0; i < 4; ++i) {
                int c = tid + i * 256;
                int r = c >> 5, ch = c & 31;
                cp16(smb + OFF_B + st * BSTAGE + r * ROWB + ch * 16,
                     g_bh16 + (np * PANEL + r) * DIM + ch * 8);
            }
            CP_COMMIT();
        }

        const uint32_t sbh = smb + OFF_B + (p & 1) * BSTAGE;

        float a0[4][4];
        #pragma unroll
        for (int j = 0; j < 4; ++j)
            #pragma unroll
            for (int q = 0; q < 4; ++q) a0[j][q] = 0.f;

        #pragma unroll 8
        for (int kt = 0; kt < 16; ++kt) {
            const uint32_t ka = kt * 32;
            uint32_t Ah0, Ah1, Ah2, Ah3;
            ldsm4(Ah0, Ah1, Ah2, Ah3, aHiA + ka);
            uint32_t Bh[8];
            ldsm4(Bh[0], Bh[1], Bh[2], Bh[3], sbh + bOff0 + ka);
            ldsm4(Bh[4], Bh[5], Bh[6], Bh[7], sbh + bOff1 + ka);
            #pragma unroll
            for (int j = 0; j < 4; ++j)
                mma_f16(a0[j], Ah0, Ah1, Ah2, Ah3, Bh[2 * j], Bh[2 * j + 1]);
        }

        // approx scores (row-constant dropped): v = 2*dot - ||e||^2
        float va0[8], va1[8];
        #pragma unroll
        for (int j = 0; j < 4; ++j) {
            #pragma unroll
            for (int e = 0; e < 2; ++e) {
                int n = p * PANEL + 8 * j + 2 * lr + e;
                float se = ssq_s[n];
                float v0 = 2.0f * (a0[j][e] * INV_SCALE2) - se;
                float v1 = 2.0f * (a0[j][2 + e] * INV_SCALE2) - se;
                va0[2 * j + e] = v0;
                va1[2 * j + e] = v1;
                bv0 = fmaxf(bv0, v0);
                bv1 = fmaxf(bv1, v1);
            }
        }
        // row max across the 4 lanes of the quad
        bv0 = fmaxf(bv0, __shfl_xor_sync(0xffffffffu, bv0, 1));
        bv0 = fmaxf(bv0, __shfl_xor_sync(0xffffffffu, bv0, 2));
        bv1 = fmaxf(bv1, __shfl_xor_sync(0xffffffffu, bv1, 1));
        bv1 = fmaxf(bv1, __shfl_xor_sync(0xffffffffu, bv1, 2));
        // gate candidates vs running max - W
        const float th0 = bv0 - w0, th1 = bv1 - w1;
        #pragma unroll
        for (int q = 0; q < 8; ++q) {
            int n = p * PANEL + 8 * (q >> 1) + 2 * lr + (q & 1);
            if (va0[q] >= th0) {
                int pos = atomicAdd(&ccnt[r0], 1);
                if (pos < MAXCAND) cidx[r0 * MAXCAND + pos] = n;
            }
            if (va1[q] >= th1) {
                int pos = atomicAdd(&ccnt[r0 + 8], 1);
                if (pos < MAXCAND) cidx[(r0 + 8) * MAXCAND + pos] = n;
            }
        }
    }
    __syncthreads();

    // ---- refine: exact fp32 scores for candidates (reference rounding) ----
    for (int m = wid; m < BM; m += 8) {
        int cnt = ccnt[m];
        const float assq = rssq_s[m];
        const float* xr = input + (n0 + m) * DIM;
        float bb = -3.4e38f;
        int   bi = 0x7fffffff;
        const bool full = (cnt > MAXCAND);
        const int ncand = full ? NEMBED : cnt;
        for (int c = 0; c < ncand; ++c) {
            int e = full ? c : cidx[m * MAXCAND + c];
            const float* er = g_embed_n + e * DIM;
            float dsum = 0.0f;
            #pragma unroll
            for (int i = 0; i < 8; ++i)
                dsum += xr[lid + 32 * i] * er[lid + 32 * i];
            #pragma unroll
            for (int o = 16; o > 0; o >>= 1)
                dsum += __shfl_xor_sync(0xffffffffu, dsum, o);
            float v = -((assq - 2.0f * dsum) + ssq_s[e]);
            if (v > bb || (v == bb && e < bi)) { bb = v; bi = e; }
        }
        if (lid == 0) {
            best_s[m] = bi;
            ind_out[n0 + m] = (float)bi;
        }
    }
    __syncthreads();

    // ---- gather + out + MSE (col = tid; input re-read, L2-hot) ----
    float dsum = 0.0f;
    for (int m = 0; m < BM; ++m) {
        int e   = best_s[m];
        float q = g_embed_n[e * DIM + tid];
        float x = input[(n0 + m) * DIM + tid];
        float q1 = x + (q - x);
        out[(n0 + m) * DIM + tid] = (q + q1) * 0.5f;
        float dd = q - x;
        dsum += dd * dd;
    }
    #pragma unroll
    for (int o = 16; o > 0; o >>= 1) dsum += __shfl_xor_sync(0xffffffffu, dsum, o);
    if ((tid & 31) == 0) red[tid >> 5] = dsum;
    __syncthreads();
    if (tid == 0) {
        float tot = 0.0f;
        #pragma unroll
        for (int k = 0; k < 8; ++k) tot += red[k];
        atomicAdd(&g_diff, tot);
    }
    (void)wr0;
}

// ---------------------------------------------------------------- loss ----
__global__ void final_kernel(float* __restrict__ loss_out) {
    __shared__ float w[8];
    int t = threadIdx.x;
    float v = g_sum[t];
    float s = v * v;
    #pragma unroll
    for (int o = 16; o > 0; o >>= 1) s += __shfl_xor_sync(0xffffffffu, s, o);
    if ((t & 31) == 0) w[t >> 5] = s;
    __syncthreads();
    if (t == 0) {
        float snorm2 = 0.0f;
        #pragma unroll
        for (int k = 0; k < 8; ++k) snorm2 += w[k];
        float entropy = 2.0f * (float)NEMBED * g_ssqsum - 2.0f * snorm2;
        float diff = g_diff * (1.0f / (float)OUT_ELEMS);
        loss_out[0] = diff - entropy * (1.0f / ((float)NEMBED * (float)NEMBED));
    }
}

// -------------------------------------------------------------- launch ----
extern "C" void kernel_launch(void* const* d_in, const int* in_sizes, int n_in,
                              void* d_out, int out_size) {
    const float* input     = (const float*)d_in[0];
    const float* embedding = (const float*)d_in[1];
    float* out  = (float*)d_out;
    float* loss = out + LOSS_OFF;
    float* ind  = out + IND_OFF;

    cudaFuncSetAttribute(main_kernel,
                         cudaFuncAttributeMaxDynamicSharedMemorySize, SMEM_BYTES);

    init_kernel<<<1, 256>>>();
    normalize_kernel<<<NEMBED, 256>>>(embedding);
    main_kernel<<<NROWS / BM, 256, SMEM_BYTES>>>(input, out, ind);
    final_kernel<<<1, 256>>>(loss);
}

// round 8
// speedup vs baseline: 1.1291x; 1.1291x over previous
#include <cuda_runtime.h>
#include <cuda_fp16.h>
#include <cstdint>

#define DIM     256
#define NEMBED  512
#define NROWS   131072
#define OUT_ELEMS 33554432
#define LOSS_OFF  33554432
#define IND_OFF   33554433

#define BM 128
#define PANEL 32
#define NPANEL (NEMBED / PANEL)   // 16
#define KLD 264                   // halves per row; 528B stride = 4 banks mod 32
#define SCALE 2048.0f             // 2^11
#define INV_SCALE2 2.38418579e-07f // 2^-22 exact
#define NTHREADS 512

#define ROWB (KLD * 2)            // 528 B
#define OFF_AHI  0
#define OFF_ALO  (OFF_AHI + BM * ROWB)       // 67584
#define OFF_B    (OFF_ALO + BM * ROWB)       // 135168
#define BSTAGE_H (PANEL * ROWB)              // 16896
#define BSTAGE   (2 * BSTAGE_H)              // 33792 (hi+lo per stage)
#define OFF_SSQ  (OFF_B + 2 * BSTAGE)        // 202752
#define OFF_RSSQ (OFF_SSQ + NEMBED * 4)      // 204800
#define OFF_BV   (OFF_RSSQ + BM * 4)         // 205312 (2*128 f)
#define OFF_BI   (OFF_BV + 2 * BM * 4)       // 206336 (2*128 i)
#define OFF_BEST (OFF_BI + 2 * BM * 4)       // 207360 (128 i)
#define OFF_RED  (OFF_BEST + BM * 4)         // 207872 (16 f)
#define SMEM_BYTES (OFF_RED + 64)            // 207936

__device__ float  g_embed_n[NEMBED * DIM];
__device__ __half g_bh16[NEMBED * DIM];
__device__ __half g_bl16[NEMBED * DIM];
__device__ float  g_ssq[NEMBED];
__device__ float  g_sum[DIM];
__device__ float  g_ssqsum;
__device__ float  g_diff;

__device__ __forceinline__ uint32_t smem_u32(const void* p) {
    uint32_t a;
    asm("{ .reg .u64 t; cvta.to.shared.u64 t, %1; cvt.u32.u64 %0, t; }" : "=r"(a) : "l"(p));
    return a;
}
__device__ __forceinline__ void mma_f16(float* d, uint32_t a0, uint32_t a1,
                                        uint32_t a2, uint32_t a3,
                                        uint32_t b0, uint32_t b1) {
    asm volatile(
        "mma.sync.aligned.m16n8k16.row.col.f32.f16.f16.f32 "
        "{%0,%1,%2,%3}, {%4,%5,%6,%7}, {%8,%9}, {%0,%1,%2,%3};"
        : "+f"(d[0]), "+f"(d[1]), "+f"(d[2]), "+f"(d[3])
        : "r"(a0), "r"(a1), "r"(a2), "r"(a3), "r"(b0), "r"(b1));
}
__device__ __forceinline__ void ldsm4(uint32_t& r0, uint32_t& r1,
                                      uint32_t& r2, uint32_t& r3, uint32_t addr) {
    asm volatile("ldmatrix.sync.aligned.m8n8.x4.shared.b16 {%0,%1,%2,%3}, [%4];"
                 : "=r"(r0), "=r"(r1), "=r"(r2), "=r"(r3) : "r"(addr));
}
__device__ __forceinline__ void cp16(uint32_t dst, const void* src) {
    asm volatile("cp.async.cg.shared.global [%0], [%1], 16;" :: "r"(dst), "l"(src) : "memory");
}
#define CP_COMMIT() asm volatile("cp.async.commit_group;" ::: "memory")
#define CP_WAIT0()  asm volatile("cp.async.wait_group 0;" ::: "memory")

// ---------------------------------------------------------------- init ----
__global__ void init_kernel() {
    int t = threadIdx.x;
    g_sum[t] = 0.0f;
    if (t == 0) { g_ssqsum = 0.0f; g_diff = 0.0f; }
}

// ------------------------------------- normalize + fp16 split (scaled) ----
__global__ void normalize_kernel(const float* __restrict__ emb) {
    __shared__ float w[8];
    int r = blockIdx.x, t = threadIdx.x;
    float v = emb[r * DIM + t];
    float s = v * v;
    #pragma unroll
    for (int o = 16; o > 0; o >>= 1) s += __shfl_xor_sync(0xffffffffu, s, o);
    if ((t & 31) == 0) w[t >> 5] = s;
    __syncthreads();
    float sum = 0.0f;
    #pragma unroll
    for (int k = 0; k < 8; ++k) sum += w[k];
    float en = __fdiv_rn(v, __fsqrt_rn(sum));
    g_embed_n[r * DIM + t] = en;
    float sc = en * SCALE;
    __half h = __float2half_rn(sc);
    g_bh16[r * DIM + t] = h;
    g_bl16[r * DIM + t] = __float2half_rn(sc - __half2float(h));
    atomicAdd(&g_sum[t], en);

    float s2 = en * en;
    #pragma unroll
    for (int o = 16; o > 0; o >>= 1) s2 += __shfl_xor_sync(0xffffffffu, s2, o);
    __syncthreads();
    if ((t & 31) == 0) w[t >> 5] = s2;
    __syncthreads();
    if (t == 0) {
        float tot = 0.0f;
        #pragma unroll
        for (int k = 0; k < 8; ++k) tot += w[k];
        g_ssq[r] = tot;
        atomicAdd(&g_ssqsum, tot);
    }
}

// ------------------------------------------------------------- main ----
__global__ void __launch_bounds__(NTHREADS, 1)
main_kernel(const float* __restrict__ input,
            float* __restrict__ out,
            float* __restrict__ ind_out) {
    extern __shared__ char sm[];
    const uint32_t smb = smem_u32(sm);
    __half* ahi   = (__half*)(sm + OFF_AHI);
    __half* alo   = (__half*)(sm + OFF_ALO);
    float*  ssq_s = (float*)(sm + OFF_SSQ);
    float*  rssq_s= (float*)(sm + OFF_RSSQ);
    float*  bvp   = (float*)(sm + OFF_BV);
    int*    bip   = (int*)(sm + OFF_BI);
    int*    best_s= (int*)(sm + OFF_BEST);
    float*  red   = (float*)(sm + OFF_RED);

    const int tid = threadIdx.x;
    const int wid = tid >> 5;
    const int lid = tid & 31;
    const int lq  = lid >> 2;
    const int lr  = lid & 3;
    const int wm  = wid & 7;          // M warp (rows 16*wm..)
    const int wn  = wid >> 3;         // N half (tiles 2wn, 2wn+1)
    const size_t n0 = (size_t)blockIdx.x * BM;

    // ---- prefetch B panel 0 (hi+lo) into stage 0 ----
    #pragma unroll
    for (int i = 0; i < 4; ++i) {
        int c = tid + i * NTHREADS;              // 0..2047
        int half = c >> 10;
        int r = (c >> 5) & 31, ch = c & 31;
        const __half* src = (half ? g_bl16 : g_bh16) + r * DIM + ch * 8;
        cp16(smb + OFF_B + half * BSTAGE_H + r * ROWB + ch * 16, src);
    }
    CP_COMMIT();

    // ---- load input tile, scale, split to fp16 hi/lo (512 threads) ----
    #pragma unroll
    for (int i = 0; i < 16; ++i) {
        int slot = tid + i * NTHREADS;           // 0..8191
        int m = slot >> 6, c4 = slot & 63;
        float4 v = *(const float4*)(input + (n0 + m) * DIM + c4 * 4);
        float sx = v.x * SCALE, sy = v.y * SCALE, sz = v.z * SCALE, sw = v.w * SCALE;
        __half hx = __float2half_rn(sx), hy = __float2half_rn(sy);
        __half hz = __float2half_rn(sz), hw = __float2half_rn(sw);
        __half lx = __float2half_rn(sx - __half2float(hx));
        __half ly = __float2half_rn(sy - __half2float(hy));
        __half lz = __float2half_rn(sz - __half2float(hz));
        __half lw = __float2half_rn(sw - __half2float(hw));
        int ho = m * KLD + c4 * 4;
        *(__half2*)(ahi + ho)     = __halves2half2(hx, hy);
        *(__half2*)(ahi + ho + 2) = __halves2half2(hz, hw);
        *(__half2*)(alo + ho)     = __halves2half2(lx, ly);
        *(__half2*)(alo + ho + 2) = __halves2half2(lz, lw);
    }
    ssq_s[tid] = g_ssq[tid];

    // ---- per-row ||x||^2 — EXACT same order/threads as passing kernels ----
    if (tid < 256) {
        int m = tid >> 1, half = tid & 1;
        const float* xr = input + (n0 + m) * DIM + half * 128;
        float s = 0.0f;
        #pragma unroll 8
        for (int k = 0; k < 128; ++k) s += xr[k] * xr[k];
        s += __shfl_xor_sync(0xffffffffu, s, 1);
        if (half == 0) rssq_s[m] = s;
    }

    // ---- ldmatrix addresses ----
    const int rowin = lid & 7;
    const int mi    = lid >> 3;
    const int aRow  = wm * 16 + rowin + 8 * (mi & 1);
    const uint32_t aHiA = smb + OFF_AHI + (uint32_t)(aRow * ROWB + (mi >> 1) * 16);
    const uint32_t aLoA = aHiA + (OFF_ALO - OFF_AHI);
    const uint32_t bOff = (uint32_t)((8 * (2 * wn + (mi >> 1)) + rowin) * ROWB + (mi & 1) * 16);

    const int r0 = wm * 16 + lq;
    float bv0 = -3.4e38f, bv1 = -3.4e38f;
    int   bi0 = 0x7fffffff, bi1 = 0x7fffffff;

    for (int p = 0; p < NPANEL; ++p) {
        CP_WAIT0();
        __syncthreads();
        if (p + 1 < NPANEL) {
            const int np = p + 1, st = np & 1;
            #pragma unroll
            for (int i = 0; i < 4; ++i) {
                int c = tid + i * NTHREADS;
                int half = c >> 10;
                int r = (c >> 5) & 31, ch = c & 31;
                const __half* src = (half ? g_bl16 : g_bh16) + (np * PANEL + r) * DIM + ch * 8;
                cp16(smb + OFF_B + st * BSTAGE + half * BSTAGE_H + r * ROWB + ch * 16, src);
            }
            CP_COMMIT();
        }

        const uint32_t sbh = smb + OFF_B + (p & 1) * BSTAGE;
        const uint32_t sbl = sbh + BSTAGE_H;

        float a0[2][4], a1[2][4], a2[2][4];
        #pragma unroll
        for (int j = 0; j < 2; ++j)
            #pragma unroll
            for (int q = 0; q < 4; ++q) { a0[j][q] = 0.f; a1[j][q] = 0.f; a2[j][q] = 0.f; }

        #pragma unroll 8
        for (int kt = 0; kt < 16; ++kt) {
            const uint32_t ka = kt * 32;
            uint32_t Ah0, Ah1, Ah2, Ah3, Al0, Al1, Al2, Al3;
            ldsm4(Ah0, Ah1, Ah2, Ah3, aHiA + ka);
            ldsm4(Al0, Al1, Al2, Al3, aLoA + ka);
            uint32_t Bh[4], Bl[4];
            ldsm4(Bh[0], Bh[1], Bh[2], Bh[3], sbh + bOff + ka);
            ldsm4(Bl[0], Bl[1], Bl[2], Bl[3], sbl + bOff + ka);
            #pragma unroll
            for (int j = 0; j < 2; ++j) {
                mma_f16(a0[j], Ah0, Ah1, Ah2, Ah3, Bh[2 * j], Bh[2 * j + 1]);
                mma_f16(a1[j], Ah0, Ah1, Ah2, Ah3, Bl[2 * j], Bl[2 * j + 1]);
                mma_f16(a2[j], Al0, Al1, Al2, Al3, Bh[2 * j], Bh[2 * j + 1]);
            }
        }

        // fold panel into running argmax (reference rounding, first-index ties)
        const float assq0 = rssq_s[r0];
        const float assq1 = rssq_s[r0 + 8];
        #pragma unroll
        for (int j = 0; j < 2; ++j) {
            #pragma unroll
            for (int e = 0; e < 2; ++e) {
                int n = p * PANEL + 8 * (2 * wn + j) + 2 * lr + e;
                float se = ssq_s[n];
                float d0 = (a0[j][e] + a1[j][e] + a2[j][e]) * INV_SCALE2;
                float d1 = (a0[j][2 + e] + a1[j][2 + e] + a2[j][2 + e]) * INV_SCALE2;
                float v0 = -((assq0 - 2.0f * d0) + se);
                float v1 = -((assq1 - 2.0f * d1) + se);
                if (v0 > bv0 || (v0 == bv0 && n < bi0)) { bv0 = v0; bi0 = n; }
                if (v1 > bv1 || (v1 == bv1 && n < bi1)) { bv1 = v1; bi1 = n; }
            }
        }
    }

    // reduce across the 4 lanes sharing each row (within warp)
    #pragma unroll
    for (int off = 1; off < 4; off <<= 1) {
        float o0 = __shfl_xor_sync(0xffffffffu, bv0, off);
        int   i0 = __shfl_xor_sync(0xffffffffu, bi0, off);
        if (o0 > bv0 || (o0 == bv0 && i0 < bi0)) { bv0 = o0; bi0 = i0; }
        float o1 = __shfl_xor_sync(0xffffffffu, bv1, off);
        int   i1 = __shfl_xor_sync(0xffffffffu, bi1, off);
        if (o1 > bv1 || (o1 == bv1 && i1 < bi1)) { bv1 = o1; bi1 = i1; }
    }
    if (lr == 0) {
        bvp[wn * BM + r0]     = bv0;
        bip[wn * BM + r0]     = bi0;
        bvp[wn * BM + r0 + 8] = bv1;
        bip[wn * BM + r0 + 8] = bi1;
    }
    __syncthreads();

    // merge the two N-halves (lexicographic (v, idx)) — threads 0..127
    if (tid < BM) {
        float v0 = bvp[tid];
        int   i0 = bip[tid];
        float v1 = bvp[BM + tid];
        int   i1 = bip[BM + tid];
        int   bi = (v1 > v0 || (v1 == v0 && i1 < i0)) ? i1 : i0;
        best_s[tid] = bi;
        ind_out[n0 + tid] = (float)bi;
    }
    __syncthreads();

    // ---- gather + out + MSE; 512 threads: row-halves for 2x parallelism ----
    {
        const int col  = tid & 255;
        const int mlo  = (tid >> 8) * 64;        // 0 or 64
        float dsum = 0.0f;
        #pragma unroll 4
        for (int mm = 0; mm < 64; ++mm) {
            int m = mlo + mm;
            int e   = best_s[m];
            float q = g_embed_n[e * DIM + col];
            float x = input[(n0 + m) * DIM + col];
            float q1 = x + (q - x);
            out[(n0 + m) * DIM + col] = (q + q1) * 0.5f;
            float dd = q - x;
            dsum += dd * dd;
        }
        #pragma unroll
        for (int o = 16; o > 0; o >>= 1) dsum += __shfl_xor_sync(0xffffffffu, dsum, o);
        if (lid == 0) red[wid] = dsum;
    }
    __syncthreads();
    if (tid == 0) {
        float tot = 0.0f;
        #pragma unroll
        for (int k = 0; k < 16; ++k) tot += red[k];
        atomicAdd(&g_diff, tot);
    }
}

// ---------------------------------------------------------------- loss ----
__global__ void final_kernel(float* __restrict__ loss_out) {
    __shared__ float w[8];
    int t = threadIdx.x;
    float v = g_sum[t];
    float s = v * v;
    #pragma unroll
    for (int o = 16; o > 0; o >>= 1) s += __shfl_xor_sync(0xffffffffu, s, o);
    if ((t & 31) == 0) w[t >> 5] = s;
    __syncthreads();
    if (t == 0) {
        float snorm2 = 0.0f;
        #pragma unroll
        for (int k = 0; k < 8; ++k) snorm2 += w[k];
        float entropy = 2.0f * (float)NEMBED * g_ssqsum - 2.0f * snorm2;
        float diff = g_diff * (1.0f / (float)OUT_ELEMS);
        loss_out[0] = diff - entropy * (1.0f / ((float)NEMBED * (float)NEMBED));
    }
}

// -------------------------------------------------------------- launch ----
extern "C" void kernel_launch(void* const* d_in, const int* in_sizes, int n_in,
                              void* d_out, int out_size) {
    const float* input     = (const float*)d_in[0];
    const float* embedding = (const float*)d_in[1];
    float* out  = (float*)d_out;
    float* loss = out + LOSS_OFF;
    float* ind  = out + IND_OFF;

    cudaFuncSetAttribute(main_kernel,
                         cudaFuncAttributeMaxDynamicSharedMemorySize, SMEM_BYTES);

    init_kernel<<<1, 256>>>();
    normalize_kernel<<<NEMBED, 256>>>(embedding);
    main_kernel<<<NROWS / BM, NTHREADS, SMEM_BYTES>>>(input, out, ind);
    final_kernel<<<1, 256>>>(loss);
}